// round 9
// baseline (speedup 1.0000x reference)
#include <cuda_runtime.h>
#include <cuda_bf16.h>

// BSplineNN: out[b,c] = sum_n coef[b,n,c] * B_{n,3}(x_b)
// B=4096, n=64, C=256, K=3, T=68.
// TWO warps per row (each: 128 channels), 8192 warps total for latency
// hiding. R8 chain per warp:
//  - span via count: lane l<=16 loads knots[4l..4l+3] with ONE LDG.128,
//    counts t<=x, __reduce_add -> j = count-1.
//  - tv window knot loads (L1 hits) issued BEFORE coef loads (per-SM
//    L1tex FIFO: completion order = issue order).
//  - 4x coef LDG.128 (DRAM) -> closed-form weights overlap the latency.
// Interior spans: guard-free closed form; edges: guarded recurrence.

#define NB    4096
#define NCOEF 64
#define NCH   256
#define NT    68
#define WARPS_PER_BLOCK 4
#define ROWS_PER_BLOCK  2   // 2 warps per row

__device__ __forceinline__ float gdiv(float a, float d) {
    return (d == 0.0f) ? 0.0f : __fdividef(a, d);
}

__global__ __launch_bounds__(WARPS_PER_BLOCK * 32)
void bspline_kernel(const float* __restrict__ coef,   // [B, 64, 256]
                    const float* __restrict__ knots,  // [B, 68]
                    const float* __restrict__ inpce,  // [B, 1]
                    float* __restrict__ out)          // [B, 256]
{
    const int warp = threadIdx.x >> 5;
    const int lane = threadIdx.x & 31;
    const int b    = blockIdx.x * ROWS_PER_BLOCK + (warp >> 1);
    const int half = warp & 1;

    const float* kt = knots + b * NT;
    const float  x  = __ldg(inpce + b);    // broadcast

    // ---- phase A: one LDG.128 per lane covers all 68 knots ----
    float4 kv = __ldg((const float4*)kt + min(lane, 16));
    int cnt = 0;
    if (lane <= 16) {
        cnt = (kv.x <= x) + (kv.y <= x) + (kv.z <= x) + (kv.w <= x);
    }
    const int total = __reduce_add_sync(0xffffffffu, cnt);   // #knots <= x
    const int j     = total - 1;                             // span candidate
    const bool valid = (total >= 1 && total <= NT - 1);      // t[j]<=x<t[j+1]
    const int jc = valid ? j : 3;

    // ---- tv window loads FIRST (L1 hits, front of LSU FIFO) ----
    float tv[8];
    #pragma unroll
    for (int m = 0; m < 8; m++) {
        tv[m] = __ldg(kt + min(max(jc - 3 + m, 0), NT - 1));   // tv[m] = t[jc-3+m]
    }

    // ---- coef loads (DRAM): 4 rows x 128 channels for this half ----
    const int n0 = min(max(jc - 3, 0), NCOEF - 1);
    const int n1 = min(max(jc - 2, 0), NCOEF - 1);
    const int n2 = min(max(jc - 1, 0), NCOEF - 1);
    const int n3 = min(max(jc,     0), NCOEF - 1);

    const float4* cr = (const float4*)(coef + (long long)b * (NCOEF * NCH));
    const int c4 = half * 32 + lane;               // float4 index within 64-float4 row

    float4 r0 = __ldg(cr + n0 * 64 + c4);
    float4 r1 = __ldg(cr + n1 * 64 + c4);
    float4 r2 = __ldg(cr + n2 * 64 + c4);
    float4 r3 = __ldg(cr + n3 * 64 + c4);

    // ---- weights from tv registers (overlap coef DRAM latency) ----
    float w0 = 0.f, w1 = 0.f, w2 = 0.f, w3 = 0.f;
    if (valid && j >= 3 && j <= NCOEF - 1) {
        // Interior: no clamp distortion; t[j]<=x<t[j+1] => all denoms > 0.
        float t0 = tv[1], t1 = tv[2], t2 = tv[3];
        float t3 = tv[4], t4 = tv[5], t5 = tv[6];

        float i1  = __fdividef(1.0f, t3 - t2);
        float b1m = (t3 - x) * i1;
        float b1c = (x - t2) * i1;

        float i20 = __fdividef(1.0f, t3 - t1);
        float i21 = __fdividef(1.0f, t4 - t2);
        float b2a = (t3 - x) * i20 * b1m;
        float b2b = (x - t1) * i20 * b1m + (t4 - x) * i21 * b1c;
        float b2c = (x - t2) * i21 * b1c;

        float i30 = __fdividef(1.0f, t3 - t0);
        float i31 = __fdividef(1.0f, t4 - t1);
        float i32 = __fdividef(1.0f, t5 - t2);
        w0 = (t3 - x) * i30 * b2a;
        w1 = (x - t0) * i30 * b2a + (t4 - x) * i31 * b2b;
        w2 = (x - t1) * i31 * b2b + (t5 - x) * i32 * b2c;
        w3 = (x - t2) * i32 * b2c;
    } else if (valid) {
        // Edge spans: fully guarded reference recurrence on the tv window.
        #define TV(i) tv[(i) - (j - 3)]
        float B1[4];
        #pragma unroll
        for (int q = 0; q < 4; q++) {
            int i = j - 2 + q;
            float v = 0.f;
            if (i >= 0 && i <= NT - 3) {
                if (i == j)     v += gdiv(x - TV(i),     TV(i + 1) - TV(i));
                if (i + 1 == j) v += gdiv(TV(i + 2) - x, TV(i + 2) - TV(i + 1));
            }
            B1[q] = v;
        }
        float B2[5];
        #pragma unroll
        for (int q = 0; q < 5; q++) {
            int i = j - 3 + q;
            float v = 0.f;
            if (i >= 0 && i <= NT - 4) {
                float a1 = gdiv(x - TV(i),     TV(i + 2) - TV(i));
                float a2 = gdiv(TV(i + 3) - x, TV(i + 3) - TV(i + 1));
                float u1 = (q >= 1) ? B1[q - 1] : 0.f;
                float u2 = (q <= 3) ? B1[q]     : 0.f;
                v = a1 * u1 + a2 * u2;
            }
            B2[q] = v;
        }
        #pragma unroll
        for (int q = 0; q < 4; q++) {
            int n = j - 3 + q;
            float v = 0.f;
            if (n >= 0 && n <= NT - 5) {
                float a1 = gdiv(x - TV(n),     TV(n + 3) - TV(n));
                float a2 = gdiv(TV(n + 4) - x, TV(n + 4) - TV(n + 1));
                v = a1 * B2[q] + a2 * B2[q + 1];
            }
            if (q == 0) w0 = v; else if (q == 1) w1 = v;
            else if (q == 2) w2 = v; else w3 = v;
        }
        #undef TV
    }

    // ---- combine + store ----
    float4 a;
    a.x = w0 * r0.x + w1 * r1.x + w2 * r2.x + w3 * r3.x;
    a.y = w0 * r0.y + w1 * r1.y + w2 * r2.y + w3 * r3.y;
    a.z = w0 * r0.z + w1 * r1.z + w2 * r2.z + w3 * r3.z;
    a.w = w0 * r0.w + w1 * r1.w + w2 * r2.w + w3 * r3.w;

    ((float4*)(out + (long long)b * NCH))[c4] = a;
}

extern "C" void kernel_launch(void* const* d_in, const int* in_sizes, int n_in,
                              void* d_out, int out_size) {
    const float* coef  = (const float*)d_in[0];  // [4096, 64, 256]
    const float* knots = (const float*)d_in[1];  // [4096, 68]
    const float* inpce = (const float*)d_in[2];  // [4096, 1]
    float* out = (float*)d_out;                  // [4096, 256]

    bspline_kernel<<<NB / ROWS_PER_BLOCK, WARPS_PER_BLOCK * 32>>>(coef, knots, inpce, out);
}